// round 14
// baseline (speedup 1.0000x reference)
#include <cuda_runtime.h>
#include <cuda_fp16.h>
#include <cstdint>

// ---------------------------------------------------------------------------
// VQ codebook assignment, N=32768 rows, K=8192 codes, D=256 (fp32).
// Phase 0: convert E to fp16 scratch; exact fp32 e_sq + max||e||^2.
// Phase 1: fp16 m16n8k16 mma.sync GEMM (ldmatrix-fed, X converted inline),
//          256 threads / 64x32 warp tiles, per-8-code-group approx minima
//          -> fp16 scratch (64 MB).  (AT the legacy-mma roofline; untouched.)
// Phase 2: wide-load (uint4, MLP=4) gmin scan, half2 min, mask-compacted
//          candidates, exact fp32 rescore within certified margin, gather.
// R14 vs R13: p2 scan rebuilt (bandwidth + issue efficiency).
// ---------------------------------------------------------------------------

#define NROWS   32768
#define NCODES  8192
#define DIM     256

#define BM      128                   // rows per CTA (phase 1)
#define BN      128                   // codes per chunk
#define NCHUNKS (NCODES / BN)         // 64
#define NKC     8                     // 32-dim stages per chunk
#define NSTG    4
#define THREADS 256
#define NGRP    (NCODES / 8)          // 1024 8-code groups

#define XPB     528                   // X smem row pitch bytes (264 fp16)
#define EPB     80                    // E smem row pitch bytes (40 fp16)
#define ESTG    (BM * EPB)            // 10240 per stage

#define SM_X    0
#define SM_E    (BM * XPB)                        // 67584
#define SM_ESQ  (SM_E + NSTG * ESTG)              // 108544
#define SMEM_TOTAL (SM_ESQ + 512 + 256)           // 109312

__device__ float          g_esq[NCODES];
__device__ unsigned int   g_emax2b;               // max ||e||^2 (ordered bits)
__device__ __half         g_ehf[(size_t)NCODES * DIM];   // 4 MB
__device__ __half         g_gmin[(size_t)NROWS * NGRP];  // 64 MB

// ---------------- helpers ----------------
__device__ __forceinline__ uint32_t smem_u32(const void* p) {
    uint32_t a;
    asm("{ .reg .u64 t; cvta.to.shared.u64 t, %1; cvt.u32.u64 %0, t; }" : "=r"(a) : "l"(p));
    return a;
}
__device__ __forceinline__ uint32_t h2pk(float lo, float hi) {  // {hi:hi, lo:lo}
    uint32_t r;
    asm("cvt.rn.f16x2.f32 %0, %1, %2;" : "=r"(r) : "f"(hi), "f"(lo));
    return r;
}
__device__ __forceinline__ void mma_f16(float* c, const uint32_t* a, const uint32_t* b) {
    asm volatile(
        "mma.sync.aligned.m16n8k16.row.col.f32.f16.f16.f32 "
        "{%0,%1,%2,%3}, {%4,%5,%6,%7}, {%8,%9}, {%0,%1,%2,%3};"
        : "+f"(c[0]), "+f"(c[1]), "+f"(c[2]), "+f"(c[3])
        : "r"(a[0]), "r"(a[1]), "r"(a[2]), "r"(a[3]), "r"(b[0]), "r"(b[1]));
}
__device__ __forceinline__ void ldsm_x4(uint32_t* r, uint32_t addr) {
    asm volatile("ldmatrix.sync.aligned.m8n8.x4.shared.b16 {%0,%1,%2,%3}, [%4];"
                 : "=r"(r[0]), "=r"(r[1]), "=r"(r[2]), "=r"(r[3]) : "r"(addr));
}
__device__ __forceinline__ unsigned long long mk_key(float v, int idx) {
    uint32_t u = __float_as_uint(v);
    u ^= (u & 0x80000000u) ? 0xFFFFFFFFu : 0x80000000u;
    return ((unsigned long long)u << 32) | (uint32_t)idx;
}
__device__ __forceinline__ unsigned long long umin64(unsigned long long a,
                                                     unsigned long long b) {
    return a < b ? a : b;
}

// one E stage: 128 codes x 32 dims fp16 (64 B/row); 256 threads, 2x16 B each
__device__ __forceinline__ void issue_stage(uint32_t sbase, int s, int tid) {
    const int chunk = s >> 3, kc = s & 7, buf = s & (NSTG - 1);
    const int r = tid >> 1, h = tid & 1;
    const __half* src = g_ehf + (size_t)(chunk * BN + r) * DIM + kc * 32 + h * 16;
    uint32_t dst = sbase + SM_E + (uint32_t)(buf * ESTG + r * EPB + h * 32);
    asm volatile("cp.async.cg.shared.global [%0], [%1], 16;" :: "r"(dst),      "l"(src)     : "memory");
    asm volatile("cp.async.cg.shared.global [%0], [%1], 16;" :: "r"(dst + 16), "l"(src + 8) : "memory");
}

// ---------------------------------------------------------------------------
// Phase 0: convert E -> fp16, e_sq, max ||e||^2 (one warp per row)
// ---------------------------------------------------------------------------
__global__ void conv_e_kernel(const float* __restrict__ embed) {
    const int row  = blockIdx.x * 8 + (threadIdx.x >> 5);
    const int lane = threadIdx.x & 31;
    float s = 0.f;
    #pragma unroll
    for (int i = 0; i < 2; ++i) {
        const int off = i * 128 + lane * 4;
        float4 v = *(const float4*)(embed + (size_t)row * DIM + off);
        s = fmaf(v.x, v.x, s); s = fmaf(v.y, v.y, s);
        s = fmaf(v.z, v.z, s); s = fmaf(v.w, v.w, s);
        uint2 p = make_uint2(h2pk(v.x, v.y), h2pk(v.z, v.w));
        *(uint2*)(g_ehf + (size_t)row * DIM + off) = p;
    }
    #pragma unroll
    for (int o = 16; o; o >>= 1) s += __shfl_xor_sync(0xffffffffu, s, o);
    if (lane == 0) {
        g_esq[row] = s;
        atomicMax(&g_emax2b, __float_as_uint(s));   // positive: bit order = value order
    }
}

// ---------------------------------------------------------------------------
// Phase 1: fp16 GEMM (8 warps, 64x32 tiles) + per-8-code-group minima
// ---------------------------------------------------------------------------
__global__ void __launch_bounds__(THREADS, 2)
vq_p1_kernel(const float* __restrict__ x) {
    extern __shared__ char smem[];
    float* esq_s = (float*)(smem + SM_ESQ);
    const uint32_t sbase = smem_u32(smem);

    const int tid  = threadIdx.x;
    const int lane = tid & 31;
    const int wid  = tid >> 5;
    const int wm   = wid & 1;                 // 64-row half
    const int wn   = wid >> 1;                // 32-code quarter
    const int gq   = lane >> 2;
    const int q    = lane & 3;
    const int row0 = blockIdx.x * BM;

    issue_stage(sbase, 0, tid);
    asm volatile("cp.async.commit_group;" ::: "memory");
    issue_stage(sbase, 1, tid);
    asm volatile("cp.async.commit_group;" ::: "memory");
    issue_stage(sbase, 2, tid);
    asm volatile("cp.async.commit_group;" ::: "memory");

    // X tile: load fp32, convert inline to fp16, pitch 528 B (LDSM clean)
    #pragma unroll
    for (int i = 0; i < 32; ++i) {
        int idx = tid + i * THREADS;          // 0..8191 float4 chunks
        int r = idx >> 6, c4 = (idx & 63) << 2;
        float4 v = *(const float4*)(x + (size_t)(row0 + r) * DIM + c4);
        uint2 p = make_uint2(h2pk(v.x, v.y), h2pk(v.z, v.w));
        *(uint2*)(smem + SM_X + r * XPB + c4 * 2) = p;
    }

    // ldmatrix lane->address mapping (x4 = four 8x8 matrices)
    const int t = lane >> 3;
    const uint32_t a_rowsel = (uint32_t)((t & 1) * 8 + (lane & 7));
    const uint32_t a_koff   = (uint32_t)((t >> 1) * 16);             // bytes
    uint32_t abase[4];
    #pragma unroll
    for (int f = 0; f < 4; ++f)
        abase[f] = sbase + SM_X + (wm * 64 + f * 16 + a_rowsel) * XPB + a_koff;
    const uint32_t b_nsel = (uint32_t)(((lane >> 4) & 1) * 8 + (lane & 7));
    const uint32_t b_koff = (uint32_t)(((lane >> 3) & 1) * 16);      // bytes
    uint32_t bbase[2];
    #pragma unroll
    for (int jp = 0; jp < 2; ++jp)
        bbase[jp] = sbase + SM_E + (wn * 32 + jp * 16 + b_nsel) * EPB + b_koff;

    #pragma unroll 1
    for (int c = 0; c < NCHUNKS; ++c) {
        float acc[4][4][4];
        #pragma unroll
        for (int f = 0; f < 4; ++f)
            #pragma unroll
            for (int j = 0; j < 4; ++j)
                #pragma unroll
                for (int r = 0; r < 4; ++r) acc[f][j][r] = 0.f;

        #pragma unroll 1
        for (int kc = 0; kc < NKC; ++kc) {
            asm volatile("cp.async.wait_group 2;" ::: "memory");
            __syncthreads();
            if (kc == 0 && tid < BN) esq_s[tid] = g_esq[c * BN + tid];

            const int g = c * NKC + kc;
            const uint32_t ebuf = (uint32_t)((g & (NSTG - 1)) * ESTG);

            #pragma unroll
            for (int s = 0; s < 2; ++s) {     // two k16 steps per 32-dim stage
                const uint32_t ak = (uint32_t)((kc * 32 + s * 16) * 2);
                const uint32_t bk = (uint32_t)(s * 32);
                uint32_t a[4][4], b[4][2];
                #pragma unroll
                for (int f = 0; f < 4; ++f) ldsm_x4(a[f], abase[f] + ak);
                #pragma unroll
                for (int jp = 0; jp < 2; ++jp) {
                    uint32_t rr[4];
                    ldsm_x4(rr, bbase[jp] + ebuf + bk);          // non-trans
                    b[jp * 2][0]     = rr[0];  // (n0-7,  k0-7)
                    b[jp * 2][1]     = rr[1];  // (n0-7,  k8-15)
                    b[jp * 2 + 1][0] = rr[2];  // (n8-15, k0-7)
                    b[jp * 2 + 1][1] = rr[3];  // (n8-15, k8-15)
                }
                #pragma unroll
                for (int f = 0; f < 4; ++f)
                    #pragma unroll
                    for (int j = 0; j < 4; ++j)
                        mma_f16(acc[f][j], a[f], b[j]);
            }

            if (g + 3 < NCHUNKS * NKC) issue_stage(sbase, g + 3, tid);
            asm volatile("cp.async.commit_group;" ::: "memory");
        }

        // ---- per-row minima of the 4 8-code groups this warp covers
        #pragma unroll
        for (int f = 0; f < 4; ++f) {
            #pragma unroll
            for (int h = 0; h < 2; ++h) {
                float m[4];
                #pragma unroll
                for (int j = 0; j < 4; ++j) {
                    const int nloc = wn * 32 + j * 8 + 2 * q;
                    const float2 e2 = *(const float2*)(esq_s + nloc);
                    float d0 = fmaf(-2.f, acc[f][j][2 * h + 0], e2.x);
                    float d1 = fmaf(-2.f, acc[f][j][2 * h + 1], e2.y);
                    float mm = fminf(d0, d1);
                    mm = fminf(mm, __shfl_xor_sync(0xffffffffu, mm, 1));
                    mm = fminf(mm, __shfl_xor_sync(0xffffffffu, mm, 2));
                    m[j] = mm;
                }
                if (q == 0) {
                    const int row = row0 + wm * 64 + f * 16 + h * 8 + gq;
                    uint2 pk = make_uint2(h2pk(m[0], m[1]), h2pk(m[2], m[3]));
                    *(uint2*)(g_gmin + (size_t)row * NGRP + c * 16 + wn * 4) = pk;
                }
            }
        }
    }
}

// ---------------------------------------------------------------------------
// Phase 2: wide gmin scan + mask compaction + exact rescore + gather
// (1 warp per row; 8 warps per block)
// ---------------------------------------------------------------------------
__global__ void __launch_bounds__(256)
vq_p2_kernel(const float* __restrict__ x,
             const float* __restrict__ embed,
             float* __restrict__ out) {
    __shared__ float xs[8][DIM];          // 8 KB
    __shared__ short cand[8][NGRP];       // 16 KB (overflow impossible)

    const int lane = threadIdx.x & 31;
    const int w    = threadIdx.x >> 5;
    const int row  = blockIdx.x * 8 + w;

    // gmin row -> registers: 4 x uint4 per lane (MLP=4). Lane covers 64 B =
    // 32 consecutive groups: group = lane*32 + i*8 + word*2 + {0,1}
    uint4 gv4[4];
    const uint4* gsrc = (const uint4*)(g_gmin + (size_t)row * NGRP);
    #pragma unroll
    for (int i = 0; i < 4; ++i) gv4[i] = gsrc[lane * 4 + i];

    // x row -> smem, ||x||^2 on the fly
    float xn2 = 0.f;
    #pragma unroll
    for (int t = lane; t < 64; t += 32) {
        float4 v = *(const float4*)(x + (size_t)row * DIM + t * 4);
        *(float4*)(xs[w] + t * 4) = v;
        xn2 = fmaf(v.x, v.x, xn2); xn2 = fmaf(v.y, v.y, xn2);
        xn2 = fmaf(v.z, v.z, xn2); xn2 = fmaf(v.w, v.w, xn2);
    }
    #pragma unroll
    for (int o = 16; o; o >>= 1) xn2 += __shfl_xor_sync(0xffffffffu, xn2, o);

    // half2 running min over this lane's 32 groups
    __half2 hmn = __halves2half2(__ushort_as_half(0x7C00), __ushort_as_half(0x7C00));
    #pragma unroll
    for (int i = 0; i < 4; ++i) {
        hmn = __hmin2(hmn, *(__half2*)&gv4[i].x);
        hmn = __hmin2(hmn, *(__half2*)&gv4[i].y);
        hmn = __hmin2(hmn, *(__half2*)&gv4[i].z);
        hmn = __hmin2(hmn, *(__half2*)&gv4[i].w);
    }
    float2 fm = __half22float2(hmn);
    float mn = fminf(fm.x, fm.y);
    #pragma unroll
    for (int off = 16; off; off >>= 1)
        mn = fminf(mn, __shfl_xor_sync(0xffffffffu, mn, off));

    // certified: |dist err| <= 2*2^-10*||x||*||e||max each side -> 2x = 0.004
    // coeff; +0.5 fp16-storage quantization (2 sides) +0.2 slack
    const float emax = sqrtf(__uint_as_float(g_emax2b));
    const float thr  = mn + fmaf(0.004f, sqrtf(xn2) * emax, 0.7f);

    // candidate mask over this lane's 32 groups
    uint32_t mask = 0;
    #pragma unroll
    for (int i = 0; i < 4; ++i) {
        const uint32_t wds[4] = {gv4[i].x, gv4[i].y, gv4[i].z, gv4[i].w};
        #pragma unroll
        for (int wd = 0; wd < 4; ++wd) {
            float2 f = __half22float2(*(const __half2*)&wds[wd]);
            if (f.x <= thr) mask |= 1u << (i * 8 + wd * 2);
            if (f.y <= thr) mask |= 1u << (i * 8 + wd * 2 + 1);
        }
    }
    const int cnt = __popc(mask);
    int pre = cnt;                         // inclusive prefix sum
    #pragma unroll
    for (int o = 1; o < 32; o <<= 1) {
        int v = __shfl_up_sync(0xffffffffu, pre, o);
        if (lane >= o) pre += v;
    }
    const int ncand = __shfl_sync(0xffffffffu, pre, 31);
    pre -= cnt;                            // exclusive
    uint32_t mm = mask;
    int k = 0;
    while (mm) {
        const int b = __ffs(mm) - 1;
        mm &= mm - 1;
        cand[w][pre + k] = (short)(lane * 32 + b);
        ++k;
    }
    __syncwarp();

    // rescore candidates exactly (8 codes/group, 4 lanes/code, 64 dims/lane)
    unsigned long long best = ~0ull;
    const int code_off = lane >> 2;
    const int quar     = lane & 3;
    const float* xq = xs[w] + quar * 64;

    #pragma unroll 1
    for (int ci = 0; ci < ncand; ++ci) {
        const int grp  = cand[w][ci];
        const int code = grp * 8 + code_off;
        const float* er = embed + (size_t)code * DIM + quar * 64;
        float dot = 0.f;
        #pragma unroll
        for (int kk = 0; kk < 16; ++kk) {
            float4 ev = *(const float4*)(er + kk * 4);
            float4 xv = *(const float4*)(xq + kk * 4);
            dot = fmaf(ev.x, xv.x, dot); dot = fmaf(ev.y, xv.y, dot);
            dot = fmaf(ev.z, xv.z, dot); dot = fmaf(ev.w, xv.w, dot);
        }
        dot += __shfl_xor_sync(0xffffffffu, dot, 1);   // combine quarters
        dot += __shfl_xor_sync(0xffffffffu, dot, 2);
        float d = fmaf(-2.f, dot, g_esq[code]);
        unsigned long long key = mk_key(d, code);
        key = umin64(key, __shfl_xor_sync(0xffffffffu, key, 4));
        key = umin64(key, __shfl_xor_sync(0xffffffffu, key, 8));
        key = umin64(key, __shfl_xor_sync(0xffffffffu, key, 16));
        best = umin64(best, key);
    }

    const int bidx = (int)(best & 0xffffffffull);
    #pragma unroll
    for (int t = lane; t < 64; t += 32) {
        float4 qv = *(const float4*)(embed + (size_t)bidx * DIM + t * 4);
        float4 xv = *(const float4*)(xs[w] + t * 4);
        float4 o;
        o.x = (qv.x - xv.x) + xv.x; o.y = (qv.y - xv.y) + xv.y;
        o.z = (qv.z - xv.z) + xv.z; o.w = (qv.w - xv.w) + xv.w;
        *(float4*)(out + (size_t)row * DIM + t * 4) = o;
    }
    if (lane == 0)
        out[(size_t)NROWS * DIM + row] = (float)bidx;
}

// ---------------------------------------------------------------------------
extern "C" void kernel_launch(void* const* d_in, const int* in_sizes, int n_in,
                              void* d_out, int out_size) {
    const float* x     = (const float*)d_in[0];   // [32768, 256]
    const float* embed = (const float*)d_in[1];   // [8192, 256]
    float*       out   = (float*)d_out;

    cudaFuncSetAttribute(vq_p1_kernel, cudaFuncAttributeMaxDynamicSharedMemorySize,
                         SMEM_TOTAL);

    conv_e_kernel<<<NCODES / 8, 256>>>(embed);
    vq_p1_kernel<<<NROWS / BM, THREADS, SMEM_TOTAL>>>(x);
    vq_p2_kernel<<<NROWS / 8, 256>>>(x, embed, out);
}

// round 16
// speedup vs baseline: 1.0074x; 1.0074x over previous
#include <cuda_runtime.h>
#include <cuda_fp16.h>
#include <cstdint>

// ---------------------------------------------------------------------------
// VQ codebook assignment, N=32768 rows, K=8192 codes, D=256 (fp32).
// Phase 0: convert E to fp16 scratch; exact fp32 e_sq + max||e||^2.
// Phase 1 (fused): fp16 m16n8k16 mma.sync GEMM (ldmatrix-fed, X converted
//   inline), per-8-code-group approx minima -> gmin (L2-hot), then IN THE
//   SAME CTA: per-row certified-margin candidate scan + exact fp32 rescore
//   + gather. One GEMM kernel, no separate phase-2 launch.
// R16 = R15 resubmit (R15 hit a broker/container failure; audit found no
// hang/OOB/capture violation — treating as infra flake, one retry).
// ---------------------------------------------------------------------------

#define NROWS   32768
#define NCODES  8192
#define DIM     256

#define BM      128                   // rows per CTA
#define BN      128                   // codes per chunk
#define NCHUNKS (NCODES / BN)         // 64
#define NKC     8                     // 32-dim stages per chunk
#define NSTG    4
#define THREADS 256
#define NGRP    (NCODES / 8)          // 1024 8-code groups

#define XPB     528                   // X smem row pitch bytes (264 fp16)
#define EPB     80                    // E smem row pitch bytes (40 fp16)
#define ESTG    (BM * EPB)            // 10240 per stage

#define SM_X    0
#define SM_E    (BM * XPB)                        // 67584
#define SM_ESQ  (SM_E + NSTG * ESTG)              // 108544
#define SMEM_TOTAL (SM_ESQ + 512 + 256)           // 109312

__device__ float          g_esq[NCODES];
__device__ unsigned int   g_emax2b;               // max ||e||^2 (ordered bits)
__device__ __half         g_ehf[(size_t)NCODES * DIM];   // 4 MB
__device__ __half         g_gmin[(size_t)NROWS * NGRP];  // 64 MB

// ---------------- helpers ----------------
__device__ __forceinline__ uint32_t smem_u32(const void* p) {
    uint32_t a;
    asm("{ .reg .u64 t; cvta.to.shared.u64 t, %1; cvt.u32.u64 %0, t; }" : "=r"(a) : "l"(p));
    return a;
}
__device__ __forceinline__ uint32_t h2pk(float lo, float hi) {  // {hi:hi, lo:lo}
    uint32_t r;
    asm("cvt.rn.f16x2.f32 %0, %1, %2;" : "=r"(r) : "f"(hi), "f"(lo));
    return r;
}
__device__ __forceinline__ void mma_f16(float* c, const uint32_t* a, const uint32_t* b) {
    asm volatile(
        "mma.sync.aligned.m16n8k16.row.col.f32.f16.f16.f32 "
        "{%0,%1,%2,%3}, {%4,%5,%6,%7}, {%8,%9}, {%0,%1,%2,%3};"
        : "+f"(c[0]), "+f"(c[1]), "+f"(c[2]), "+f"(c[3])
        : "r"(a[0]), "r"(a[1]), "r"(a[2]), "r"(a[3]), "r"(b[0]), "r"(b[1]));
}
__device__ __forceinline__ void ldsm_x4(uint32_t* r, uint32_t addr) {
    asm volatile("ldmatrix.sync.aligned.m8n8.x4.shared.b16 {%0,%1,%2,%3}, [%4];"
                 : "=r"(r[0]), "=r"(r[1]), "=r"(r[2]), "=r"(r[3]) : "r"(addr));
}
__device__ __forceinline__ unsigned long long mk_key(float v, int idx) {
    uint32_t u = __float_as_uint(v);
    u ^= (u & 0x80000000u) ? 0xFFFFFFFFu : 0x80000000u;
    return ((unsigned long long)u << 32) | (uint32_t)idx;
}
__device__ __forceinline__ unsigned long long umin64(unsigned long long a,
                                                     unsigned long long b) {
    return a < b ? a : b;
}

// one E stage: 128 codes x 32 dims fp16 (64 B/row); 256 threads, 2x16 B each
__device__ __forceinline__ void issue_stage(uint32_t sbase, int s, int tid) {
    const int chunk = s >> 3, kc = s & 7, buf = s & (NSTG - 1);
    const int r = tid >> 1, h = tid & 1;
    const __half* src = g_ehf + (size_t)(chunk * BN + r) * DIM + kc * 32 + h * 16;
    uint32_t dst = sbase + SM_E + (uint32_t)(buf * ESTG + r * EPB + h * 32);
    asm volatile("cp.async.cg.shared.global [%0], [%1], 16;" :: "r"(dst),      "l"(src)     : "memory");
    asm volatile("cp.async.cg.shared.global [%0], [%1], 16;" :: "r"(dst + 16), "l"(src + 8) : "memory");
}

// ---------------------------------------------------------------------------
// Phase 0: convert E -> fp16, e_sq, max ||e||^2 (one warp per row)
// ---------------------------------------------------------------------------
__global__ void conv_e_kernel(const float* __restrict__ embed) {
    const int row  = blockIdx.x * 8 + (threadIdx.x >> 5);
    const int lane = threadIdx.x & 31;
    float s = 0.f;
    #pragma unroll
    for (int i = 0; i < 2; ++i) {
        const int off = i * 128 + lane * 4;
        float4 v = *(const float4*)(embed + (size_t)row * DIM + off);
        s = fmaf(v.x, v.x, s); s = fmaf(v.y, v.y, s);
        s = fmaf(v.z, v.z, s); s = fmaf(v.w, v.w, s);
        uint2 p = make_uint2(h2pk(v.x, v.y), h2pk(v.z, v.w));
        *(uint2*)(g_ehf + (size_t)row * DIM + off) = p;
    }
    #pragma unroll
    for (int o = 16; o; o >>= 1) s += __shfl_xor_sync(0xffffffffu, s, o);
    if (lane == 0) {
        g_esq[row] = s;
        atomicMax(&g_emax2b, __float_as_uint(s));   // positive: bit order = value order
    }
}

// ---------------------------------------------------------------------------
// Phase 1 (fused): fp16 GEMM + group minima + candidate rescore + gather
// ---------------------------------------------------------------------------
__global__ void __launch_bounds__(THREADS, 2)
vq_p1_kernel(const float* __restrict__ x,
             const float* __restrict__ embed,
             float* __restrict__ out) {
    extern __shared__ char smem[];
    float* esq_s = (float*)(smem + SM_ESQ);
    const uint32_t sbase = smem_u32(smem);

    const int tid  = threadIdx.x;
    const int lane = tid & 31;
    const int wid  = tid >> 5;
    const int wm   = wid & 1;                 // 64-row half
    const int wn   = wid >> 1;                // 32-code quarter
    const int gq   = lane >> 2;
    const int q    = lane & 3;
    const int row0 = blockIdx.x * BM;

    issue_stage(sbase, 0, tid);
    asm volatile("cp.async.commit_group;" ::: "memory");
    issue_stage(sbase, 1, tid);
    asm volatile("cp.async.commit_group;" ::: "memory");
    issue_stage(sbase, 2, tid);
    asm volatile("cp.async.commit_group;" ::: "memory");

    // X tile: load fp32, convert inline to fp16, pitch 528 B (LDSM clean)
    #pragma unroll
    for (int i = 0; i < 32; ++i) {
        int idx = tid + i * THREADS;          // 0..8191 float4 chunks
        int r = idx >> 6, c4 = (idx & 63) << 2;
        float4 v = *(const float4*)(x + (size_t)(row0 + r) * DIM + c4);
        uint2 p = make_uint2(h2pk(v.x, v.y), h2pk(v.z, v.w));
        *(uint2*)(smem + SM_X + r * XPB + c4 * 2) = p;
    }

    // ldmatrix lane->address mapping (x4 = four 8x8 matrices)
    const int t = lane >> 3;
    const uint32_t a_rowsel = (uint32_t)((t & 1) * 8 + (lane & 7));
    const uint32_t a_koff   = (uint32_t)((t >> 1) * 16);             // bytes
    uint32_t abase[4];
    #pragma unroll
    for (int f = 0; f < 4; ++f)
        abase[f] = sbase + SM_X + (wm * 64 + f * 16 + a_rowsel) * XPB + a_koff;
    const uint32_t b_nsel = (uint32_t)(((lane >> 4) & 1) * 8 + (lane & 7));
    const uint32_t b_koff = (uint32_t)(((lane >> 3) & 1) * 16);      // bytes
    uint32_t bbase[2];
    #pragma unroll
    for (int jp = 0; jp < 2; ++jp)
        bbase[jp] = sbase + SM_E + (wn * 32 + jp * 16 + b_nsel) * EPB + b_koff;

    #pragma unroll 1
    for (int c = 0; c < NCHUNKS; ++c) {
        float acc[4][4][4];
        #pragma unroll
        for (int f = 0; f < 4; ++f)
            #pragma unroll
            for (int j = 0; j < 4; ++j)
                #pragma unroll
                for (int r = 0; r < 4; ++r) acc[f][j][r] = 0.f;

        #pragma unroll 1
        for (int kc = 0; kc < NKC; ++kc) {
            asm volatile("cp.async.wait_group 2;" ::: "memory");
            __syncthreads();
            if (kc == 0 && tid < BN) esq_s[tid] = g_esq[c * BN + tid];

            const int g = c * NKC + kc;
            const uint32_t ebuf = (uint32_t)((g & (NSTG - 1)) * ESTG);

            #pragma unroll
            for (int s = 0; s < 2; ++s) {     // two k16 steps per 32-dim stage
                const uint32_t ak = (uint32_t)((kc * 32 + s * 16) * 2);
                const uint32_t bk = (uint32_t)(s * 32);
                uint32_t a[4][4], b[4][2];
                #pragma unroll
                for (int f = 0; f < 4; ++f) ldsm_x4(a[f], abase[f] + ak);
                #pragma unroll
                for (int jp = 0; jp < 2; ++jp) {
                    uint32_t rr[4];
                    ldsm_x4(rr, bbase[jp] + ebuf + bk);          // non-trans
                    b[jp * 2][0]     = rr[0];  // (n0-7,  k0-7)
                    b[jp * 2][1]     = rr[1];  // (n0-7,  k8-15)
                    b[jp * 2 + 1][0] = rr[2];  // (n8-15, k0-7)
                    b[jp * 2 + 1][1] = rr[3];  // (n8-15, k8-15)
                }
                #pragma unroll
                for (int f = 0; f < 4; ++f)
                    #pragma unroll
                    for (int j = 0; j < 4; ++j)
                        mma_f16(acc[f][j], a[f], b[j]);
            }

            if (g + 3 < NCHUNKS * NKC) issue_stage(sbase, g + 3, tid);
            asm volatile("cp.async.commit_group;" ::: "memory");
        }

        // ---- per-row minima of the 4 8-code groups this warp covers
        #pragma unroll
        for (int f = 0; f < 4; ++f) {
            #pragma unroll
            for (int h = 0; h < 2; ++h) {
                float m[4];
                #pragma unroll
                for (int j = 0; j < 4; ++j) {
                    const int nloc = wn * 32 + j * 8 + 2 * q;
                    const float2 e2 = *(const float2*)(esq_s + nloc);
                    float d0 = fmaf(-2.f, acc[f][j][2 * h + 0], e2.x);
                    float d1 = fmaf(-2.f, acc[f][j][2 * h + 1], e2.y);
                    float mm = fminf(d0, d1);
                    mm = fminf(mm, __shfl_xor_sync(0xffffffffu, mm, 1));
                    mm = fminf(mm, __shfl_xor_sync(0xffffffffu, mm, 2));
                    m[j] = mm;
                }
                if (q == 0) {
                    const int row = row0 + wm * 64 + f * 16 + h * 8 + gq;
                    uint2 pk = make_uint2(h2pk(m[0], m[1]), h2pk(m[2], m[3]));
                    *(uint2*)(g_gmin + (size_t)row * NGRP + c * 16 + wn * 4) = pk;
                }
            }
        }
    }

    // =======================================================================
    // Fused phase 2: this CTA's 128 rows. gmin is L2-hot (written above).
    // __syncthreads orders all warps' gmin stores before any tail reads,
    // and releases SM_X for reuse.
    // =======================================================================
    __syncthreads();

    float* xs    = (float*)(smem + wid * 1024);            // 256 fp32 per warp
    short* cand  = (short*)(smem + 8 * 1024 + wid * 2048); // 1024 shorts/warp
    const float emax = sqrtf(__uint_as_float(g_emax2b));

    #pragma unroll 1
    for (int lr = 0; lr < 16; ++lr) {
        const int row = row0 + wid * 16 + lr;

        // x row -> smem (fp32, exact), ||x||^2 on the fly
        float xn2 = 0.f;
        #pragma unroll
        for (int tt = lane; tt < 64; tt += 32) {
            float4 v = *(const float4*)(x + (size_t)row * DIM + tt * 4);
            *(float4*)(xs + tt * 4) = v;
            xn2 = fmaf(v.x, v.x, xn2); xn2 = fmaf(v.y, v.y, xn2);
            xn2 = fmaf(v.z, v.z, xn2); xn2 = fmaf(v.w, v.w, xn2);
        }
        #pragma unroll
        for (int o = 16; o; o >>= 1) xn2 += __shfl_xor_sync(0xffffffffu, xn2, o);

        // gmin row -> registers (uint4 x4 per lane, MLP=4; L2-hot)
        uint4 gv4[4];
        const uint4* gsrc = (const uint4*)(g_gmin + (size_t)row * NGRP);
        #pragma unroll
        for (int i = 0; i < 4; ++i) gv4[i] = gsrc[lane * 4 + i];

        __half2 hmn = __halves2half2(__ushort_as_half(0x7C00), __ushort_as_half(0x7C00));
        #pragma unroll
        for (int i = 0; i < 4; ++i) {
            hmn = __hmin2(hmn, *(__half2*)&gv4[i].x);
            hmn = __hmin2(hmn, *(__half2*)&gv4[i].y);
            hmn = __hmin2(hmn, *(__half2*)&gv4[i].z);
            hmn = __hmin2(hmn, *(__half2*)&gv4[i].w);
        }
        float2 fm = __half22float2(hmn);
        float mn = fminf(fm.x, fm.y);
        #pragma unroll
        for (int off = 16; off; off >>= 1)
            mn = fminf(mn, __shfl_xor_sync(0xffffffffu, mn, off));

        // certified: |dist err| <= 2*2^-10*||x||*||e||max each side -> 0.004
        // coeff (2x containment); +0.5 fp16-storage quantization +0.2 slack
        const float thr = mn + fmaf(0.004f, sqrtf(xn2) * emax, 0.7f);

        // candidate mask over this lane's 32 groups
        uint32_t mask = 0;
        #pragma unroll
        for (int i = 0; i < 4; ++i) {
            const uint32_t wds[4] = {gv4[i].x, gv4[i].y, gv4[i].z, gv4[i].w};
            #pragma unroll
            for (int wd = 0; wd < 4; ++wd) {
                float2 f = __half22float2(*(const __half2*)&wds[wd]);
                if (f.x <= thr) mask |= 1u << (i * 8 + wd * 2);
                if (f.y <= thr) mask |= 1u << (i * 8 + wd * 2 + 1);
            }
        }
        const int cnt = __popc(mask);
        int pre = cnt;
        #pragma unroll
        for (int o = 1; o < 32; o <<= 1) {
            int v = __shfl_up_sync(0xffffffffu, pre, o);
            if (lane >= o) pre += v;
        }
        const int ncand = __shfl_sync(0xffffffffu, pre, 31);
        pre -= cnt;
        uint32_t mm = mask;
        int k = 0;
        while (mm) {
            const int b = __ffs(mm) - 1;
            mm &= mm - 1;
            cand[pre + k] = (short)(lane * 32 + b);
            ++k;
        }
        __syncwarp();

        // rescore candidates exactly (8 codes/group, 4 lanes/code, 64 dims)
        unsigned long long best = ~0ull;
        const int code_off = lane >> 2;
        const int quar     = lane & 3;
        const float* xq = xs + quar * 64;

        #pragma unroll 1
        for (int ci = 0; ci < ncand; ++ci) {
            const int grp  = cand[ci];
            const int code = grp * 8 + code_off;
            const float* er = embed + (size_t)code * DIM + quar * 64;
            float dot = 0.f;
            #pragma unroll
            for (int kk = 0; kk < 16; ++kk) {
                float4 ev = *(const float4*)(er + kk * 4);
                float4 xv = *(const float4*)(xq + kk * 4);
                dot = fmaf(ev.x, xv.x, dot); dot = fmaf(ev.y, xv.y, dot);
                dot = fmaf(ev.z, xv.z, dot); dot = fmaf(ev.w, xv.w, dot);
            }
            dot += __shfl_xor_sync(0xffffffffu, dot, 1);
            dot += __shfl_xor_sync(0xffffffffu, dot, 2);
            float d = fmaf(-2.f, dot, g_esq[code]);
            unsigned long long key = mk_key(d, code);
            key = umin64(key, __shfl_xor_sync(0xffffffffu, key, 4));
            key = umin64(key, __shfl_xor_sync(0xffffffffu, key, 8));
            key = umin64(key, __shfl_xor_sync(0xffffffffu, key, 16));
            best = umin64(best, key);
        }

        const int bidx = (int)(best & 0xffffffffull);
        #pragma unroll
        for (int tt = lane; tt < 64; tt += 32) {
            float4 qv = *(const float4*)(embed + (size_t)bidx * DIM + tt * 4);
            float4 xv = *(const float4*)(xs + tt * 4);
            float4 o;
            o.x = (qv.x - xv.x) + xv.x; o.y = (qv.y - xv.y) + xv.y;
            o.z = (qv.z - xv.z) + xv.z; o.w = (qv.w - xv.w) + xv.w;
            *(float4*)(out + (size_t)row * DIM + tt * 4) = o;
        }
        if (lane == 0)
            out[(size_t)NROWS * DIM + row] = (float)bidx;
        __syncwarp();
    }
}

// ---------------------------------------------------------------------------
extern "C" void kernel_launch(void* const* d_in, const int* in_sizes, int n_in,
                              void* d_out, int out_size) {
    const float* x     = (const float*)d_in[0];   // [32768, 256]
    const float* embed = (const float*)d_in[1];   // [8192, 256]
    float*       out   = (float*)d_out;

    cudaFuncSetAttribute(vq_p1_kernel, cudaFuncAttributeMaxDynamicSharedMemorySize,
                         SMEM_TOTAL);

    conv_e_kernel<<<NCODES / 8, 256>>>(embed);
    vq_p1_kernel<<<NROWS / BM, THREADS, SMEM_TOTAL>>>(x, embed, out);
}